// round 3
// baseline (speedup 1.0000x reference)
#include <cuda_runtime.h>
#include <stdint.h>
#include <cooperative_groups.h>
namespace cg = cooperative_groups;

#define BATCH 16
#define HH 512
#define WW 512
#define WPR 16                  // 32-bit words per row
#define WPI (HH*WPR)            // 8192 words per image
#define NPIX (BATCH*HH*WW)      // 4194304
#define NBLK 1024               // kA blocks (16 px/thread, 256 thr)
#define ROWS_CTA 128            // rows per cluster CTA
#define NGRP 32                 // 4-row groups per CTA
#define SSTRIDE 18              // padded row stride
#define SBUF (ROWS_CTA*SSTRIDE) // 2304 words per buffer

// ---------------- scratch (no allocation allowed) ----------------
__device__ uint32_t g_pred[BATCH*WPI];
__device__ uint32_t g_true[BATCH*WPI];
__device__ uint32_t g_ps[BATCH*WPI];
__device__ uint32_t g_ts[BATCH*WPI];
__device__ float    g_part[5*NBLK];
__device__ float    g_cl[BATCH];
__device__ int      g_ctr;

// ---------------- kernel A: binarize + dice/focal partials -------
__global__ __launch_bounds__(256) void kA(const float* __restrict__ logits,
                                          const int*   __restrict__ tr){
    int tid = threadIdx.x;
    int gt  = blockIdx.x*256 + tid;
    long i16 = (long)gt * 16;
    int b   = (int)(i16 >> 18);
    int rem = (int)(i16 & ((1<<18)-1));

    const float4* F = (const float4*)logits;
    size_t q0 = (((size_t)(2*b)   << 18) + rem) >> 2;
    size_t q1 = (((size_t)(2*b+1) << 18) + rem) >> 2;
    const int4* T4 = (const int4*)tr;
    size_t qt = ((size_t)i16) >> 2;

    unsigned pm = 0, tm = 0;
    float s0=0.f, s1=0.f, s2=0.f, s3=0.f, s4=0.f;
    #pragma unroll
    for (int u = 0; u < 4; u++){
        float4 A = F[q0+u], B = F[q1+u];
        int4 t = T4[qt+u];
        float l0[4] = {A.x,A.y,A.z,A.w};
        float l1[4] = {B.x,B.y,B.z,B.w};
        int   tt[4] = {t.x,t.y,t.z,t.w};
        #pragma unroll
        for (int j = 0; j < 4; j++){
            float d = l1[j] - l0[j];
            bool pd = d > 0.f;
            bool tp = tt[j] > 0;
            pm |= (unsigned)pd << (u*4+j);
            tm |= (unsigned)tp << (u*4+j);
            float ad = fabsf(d);
            float e  = __expf(-ad);
            float pb = __fdividef(1.f, 1.f + e);   // sigmoid(|d|)
            float lg = -__logf(pb);                 // log(1+e^-|d|)
            float p1v = pd ? pb : 1.f - pb;
            float p0v = 1.f - p1v;
            float ce = (tp == pd) ? lg : (ad + lg);
            float pt = tp ? p1v : p0v;
            float om = 1.f - pt;
            s4 += 0.25f * om * om * ce;
            s2 += p1v;
            if (tp){ s1 += p1v; s3 += 1.f; }
            else   { s0 += p0v; }
        }
    }
    ((uint16_t*)g_pred)[gt] = (uint16_t)pm;
    ((uint16_t*)g_true)[gt] = (uint16_t)tm;

    __shared__ float red[8*5];
    int lane = tid & 31, wid = tid >> 5;
    float vals[5] = {s0, s1, s2, s3, s4};
    #pragma unroll
    for (int v = 0; v < 5; v++){
        float x = vals[v];
        #pragma unroll
        for (int o = 16; o; o >>= 1) x += __shfl_down_sync(0xffffffffu, x, o);
        if (lane == 0) red[wid*5 + v] = x;
    }
    __syncthreads();
    if (wid == 0 && lane < 5){
        float s = 0.f;
        #pragma unroll
        for (int w = 0; w < 8; w++) s += red[w*5 + lane];
        g_part[lane*NBLK + blockIdx.x] = s;
    }
}

// ---------------- kernel B: clustered, activity-gated Zhang-Suen -
// act: flat [2*NGRP], slot = SUB. mb_up/mb_dn: [3], slot rotates mod 3.
template<int SUB>
__device__ __forceinline__ void subiter(
    const uint32_t* __restrict__ src, uint32_t* __restrict__ dst,
    const uint32_t* upS, const uint32_t* dnS,
    uint32_t* __restrict__ act,
    const uint32_t* __restrict__ mb_up, const uint32_t* __restrict__ mb_dn,
    uint32_t* up_mbdn, uint32_t* dn_mbup, int mbw,
    int* s_flag_p, int g, int w, uint32_t wm, int tid)
{
    // --- phase A: activity decision (reads only; barrier before any act write)
    uint32_t am1 = (g == 0)      ? (mb_up[0] | mb_up[1] | mb_up[2])
                                 : (act[g-1] | act[NGRP + g-1]);
    uint32_t a0  = act[g] | act[NGRP + g];
    uint32_t ap1 = (g == NGRP-1) ? (mb_dn[0] | mb_dn[1] | mb_dn[2])
                                 : (act[g+1] | act[NGRP + g+1]);
    uint32_t actv = (am1 | a0 | ap1) & wm;
    __syncthreads();

    bool changed = false;
    if (actv){
        uint32_t C[6], E[6], Wm[6];
        #pragma unroll
        for (int i = 0; i < 6; i++){
            int r = 4*g - 1 + i;
            uint32_t c, l, rr;
            if (r >= 0 && r < ROWS_CTA){
                const uint32_t* row = src + r*SSTRIDE;
                c = row[w]; l = (w > 0) ? row[w-1] : 0u; rr = (w < 15) ? row[w+1] : 0u;
            } else if (r < 0){
                if (upS){
                    const uint32_t* row = upS + (ROWS_CTA-1)*SSTRIDE;
                    c = row[w]; l = (w > 0) ? row[w-1] : 0u; rr = (w < 15) ? row[w+1] : 0u;
                } else { c = l = rr = 0u; }
            } else {
                if (dnS){
                    const uint32_t* row = dnS;
                    c = row[w]; l = (w > 0) ? row[w-1] : 0u; rr = (w < 15) ? row[w+1] : 0u;
                } else { c = l = rr = 0u; }
            }
            C[i]  = c;
            E[i]  = __funnelshift_r(c, rr, 1);
            Wm[i] = __funnelshift_l(l, c, 1);
        }
        #pragma unroll
        for (int k = 0; k < 4; k++){
            int i = k + 1;
            uint32_t cC = C[i];
            uint32_t p2 = C[i-1], p3 = E[i-1], p9 = Wm[i-1];
            uint32_t p4 = E[i],   p8 = Wm[i];
            uint32_t p6 = C[i+1], p5 = E[i+1], p7 = Wm[i+1];

            // B in [2,6] via bit-sliced CSA
            uint32_t sa = p2 ^ p3 ^ p4, ca = (p2 & p3) | (p4 & (p2 ^ p3));
            uint32_t sb = p5 ^ p6 ^ p7, cb = (p5 & p6) | (p7 & (p5 ^ p6));
            uint32_t sc = p8 ^ p9,      cc = p8 & p9;
            uint32_t S0 = sa ^ sb ^ sc, cd = (sa & sb) | (sc & (sa ^ sb));
            uint32_t t1v = ca ^ cb ^ cc, c1a = (ca & cb) | (cc & (ca ^ cb));
            uint32_t S1 = t1v ^ cd,      c1b = t1v & cd;
            uint32_t S2 = c1a ^ c1b,     S3 = c1a & c1b;
            uint32_t cond1 = (S1 | S2 | S3) & ~(S3 | (S2 & S1 & S0));

            // A == 1 (exactly one 0->1 transition in cyclic p2..p9)
            uint32_t t0 = ~p2 & p3;
            uint32_t t1_ = ~p3 & p4;
            uint32_t t2 = ~p4 & p5;
            uint32_t t3 = ~p5 & p6;
            uint32_t t4 = ~p6 & p7;
            uint32_t t5 = ~p7 & p8;
            uint32_t t6 = ~p8 & p9;
            uint32_t t7 = ~p9 & p2;
            uint32_t onep = t0, two = 0;
            two |= onep & t1_; onep |= t1_;
            two |= onep & t2;  onep |= t2;
            two |= onep & t3;  onep |= t3;
            two |= onep & t4;  onep |= t4;
            two |= onep & t5;  onep |= t5;
            two |= onep & t6;  onep |= t6;
            two |= onep & t7;  onep |= t7;
            uint32_t condA = onep & ~two;

            uint32_t c3m, c4m;
            if (SUB == 0){ c3m = ~(p2 & p4 & p6); c4m = ~(p4 & p6 & p8); }
            else         { c3m = ~(p2 & p4 & p8); c4m = ~(p2 & p6 & p8); }

            uint32_t remv = cC & cond1 & condA & c3m & c4m;
            dst[(4*g + k)*SSTRIDE + w] = cC & ~remv;
            changed = changed || (remv != 0u);
        }
        if (changed) *s_flag_p = 1;
    }

    unsigned bal = __ballot_sync(0xffffffffu, changed);
    int lane = tid & 31;
    if (lane == 0 || lane == 16){
        uint32_t v = (lane == 0) ? (bal & 0xFFFFu) : (bal >> 16);
        act[SUB*NGRP + g] = v;
        if (g == 0       && up_mbdn) up_mbdn[mbw] = v;
        if (g == NGRP-1  && dn_mbup) dn_mbup[mbw] = v;
    }
}

__global__ void __cluster_dims__(4,1,1) __launch_bounds__(512) kB(){
    __shared__ uint32_t S[2][SBUF];
    __shared__ uint32_t act[2*NGRP];
    __shared__ uint32_t mb_up[3], mb_dn[3];
    __shared__ int s_flag[2];
    __shared__ int s_any;

    cg::cluster_group cl = cg::this_cluster();
    unsigned rank = cl.block_rank();
    int unit = blockIdx.x >> 2;
    int img  = unit >> 1;
    int sel  = unit & 1;
    const uint32_t* srcg = (sel ? g_true : g_pred) + img*WPI + rank*2048;
    uint32_t*       dstg = (sel ? g_ts   : g_ps)   + img*WPI + rank*2048;

    int tid = threadIdx.x;
    int g = tid >> 4, w = tid & 15;

    #pragma unroll
    for (int it = 0; it < 4; it++){
        int idx = tid + it*512;
        S[0][(idx>>4)*SSTRIDE + (idx&15)] = srcg[idx];
    }
    if (tid < NGRP){ act[tid] = 0xFFFFu; act[NGRP + tid] = 0xFFFFu; }
    if (tid == 0){
        uint32_t u = (rank > 0) ? 0xFFFFu : 0u;
        uint32_t d = (rank < 3) ? 0xFFFFu : 0u;
        mb_up[0] = mb_up[1] = mb_up[2] = u;
        mb_dn[0] = mb_dn[1] = mb_dn[2] = d;
        s_flag[0] = 1; s_flag[1] = 1;
    }

    uint32_t* upS    = (rank > 0) ? cl.map_shared_rank(&S[0][0], rank-1) : (uint32_t*)0;
    uint32_t* dnS    = (rank < 3) ? cl.map_shared_rank(&S[0][0], rank+1) : (uint32_t*)0;
    uint32_t* up_mbdn= (rank > 0) ? cl.map_shared_rank(&mb_dn[0], rank-1) : (uint32_t*)0;
    uint32_t* dn_mbup= (rank < 3) ? cl.map_shared_rank(&mb_up[0], rank+1) : (uint32_t*)0;
    int* fp0 = cl.map_shared_rank(&s_flag[0], 0);
    int* fp1 = cl.map_shared_rank(&s_flag[0], 1);
    int* fp2 = cl.map_shared_rank(&s_flag[0], 2);
    int* fp3 = cl.map_shared_rank(&s_flag[0], 3);

    cl.sync();

    uint32_t wm = (w == 0) ? 0x3u : (7u << (w - 1));
    int mbw = 0;   // mailbox write slot, rotates mod 3 per subiter
    for (int p = 0; ; p ^= 1){
        if (tid == 0){
            int q = p ^ 1;
            s_any = fp0[q] | fp1[q] | fp2[q] | fp3[q];
            s_flag[p] = 0;
        }
        __syncthreads();
        if (!s_any) break;

        subiter<0>(&S[0][0], &S[1][0],
                   upS, dnS ? dnS : (uint32_t*)0,
                   act, mb_up, mb_dn, up_mbdn, dn_mbup, mbw,
                   &s_flag[p], g, w, wm, tid);
        mbw = (mbw == 2) ? 0 : mbw + 1;
        cl.sync();

        subiter<1>(&S[1][0], &S[0][0],
                   upS ? upS + SBUF : (uint32_t*)0,
                   dnS ? dnS + SBUF : (uint32_t*)0,
                   act, mb_up, mb_dn, up_mbdn, dn_mbup, mbw,
                   &s_flag[p], g, w, wm, tid);
        mbw = (mbw == 2) ? 0 : mbw + 1;
        cl.sync();
    }

    #pragma unroll
    for (int it = 0; it < 4; it++){
        int idx = tid + it*512;
        dstg[idx] = S[0][(idx>>4)*SSTRIDE + (idx&15)];
    }
    cl.sync();   // no CTA exits while peers may still read its smem
}

// ---------------- kernel CD: clDice popcounts + final combine ----
__global__ __launch_bounds__(256) void kCD(float* __restrict__ out){
    int tid = threadIdx.x;
    if (blockIdx.x < BATCH){
        int b = blockIdx.x;
        int inter = 0, sp = 0, st = 0;
        const uint4* A  = (const uint4*)(g_ps + b*WPI);
        const uint4* Cc = (const uint4*)(g_ts + b*WPI);
        for (int k = tid; k < WPI/4; k += 256){
            uint4 a = A[k], c = Cc[k];
            inter += __popc(a.x & c.x) + __popc(a.y & c.y) + __popc(a.z & c.z) + __popc(a.w & c.w);
            sp    += __popc(a.x) + __popc(a.y) + __popc(a.z) + __popc(a.w);
            st    += __popc(c.x) + __popc(c.y) + __popc(c.z) + __popc(c.w);
        }
        __shared__ int red[8*3];
        int lane = tid & 31, wid = tid >> 5;
        int v3[3] = {inter, sp, st};
        #pragma unroll
        for (int v = 0; v < 3; v++){
            int x = v3[v];
            #pragma unroll
            for (int o = 16; o; o >>= 1) x += __shfl_down_sync(0xffffffffu, x, o);
            if (lane == 0) red[wid*3 + v] = x;
        }
        __syncthreads();
        if (tid == 0){
            int ti = 0, tp = 0, tt = 0;
            #pragma unroll
            for (int w = 0; w < 8; w++){ ti += red[w*3]; tp += red[w*3+1]; tt += red[w*3+2]; }
            g_cl[b] = (2.f*(float)ti + 1e-6f) / ((float)(tp + tt) + 1e-6f);
            __threadfence();
            atomicAdd(&g_ctr, 1);
        }
    } else {
        __shared__ float red[8*5];
        int lane = tid & 31, wid = tid >> 5;
        #pragma unroll
        for (int v = 0; v < 5; v++){
            const float4* P = (const float4*)(g_part + v*NBLK);
            float4 a = P[tid];
            float x = (a.x + a.y) + (a.z + a.w);
            #pragma unroll
            for (int o = 16; o; o >>= 1) x += __shfl_down_sync(0xffffffffu, x, o);
            if (lane == 0) red[wid*5 + v] = x;
        }
        __syncthreads();
        if (tid == 0){
            float tot[5];
            #pragma unroll
            for (int v = 0; v < 5; v++){
                float s = 0.f;
                #pragma unroll
                for (int w = 0; w < 8; w++) s += red[w*5 + v];
                tot[v] = s;
            }
            while (atomicAdd(&g_ctr, 0) < BATCH) { }
            __threadfence();
            float cls = 0.f;
            #pragma unroll
            for (int b = 0; b < BATCH; b++) cls += ((volatile float*)g_cl)[b];

            const float EPS = 1e-6f;
            float TOT = (float)NPIX;
            float s_i0 = tot[0], s_i1 = tot[1], s_p1 = tot[2], n1 = tot[3], sf = tot[4];
            float card0 = (TOT - s_p1) + (TOT - n1);
            float card1 = s_p1 + n1;
            float dice = 1.f - 0.5f * ((2.f*s_i0 + EPS)/(card0 + EPS)
                                     + (2.f*s_i1 + EPS)/(card1 + EPS));
            float cl = 1.f - cls / (float)BATCH;
            float focal = sf / TOT;
            out[0] = 0.7f*cl + 0.1f*dice + 0.2f*focal;
            atomicExch(&g_ctr, 0);   // reset for next graph replay
        }
    }
}

// ---------------- launch -----------------------------------------
extern "C" void kernel_launch(void* const* d_in, const int* in_sizes, int n_in,
                              void* d_out, int out_size){
    const float* logits = (const float*)d_in[0];
    const int*   tr     = (const int*)d_in[1];
    kA<<<NBLK, 256>>>(logits, tr);
    kB<<<8*BATCH, 512>>>();
    kCD<<<BATCH+1, 256>>>((float*)d_out);
}

// round 5
// speedup vs baseline: 1.0536x; 1.0536x over previous
#include <cuda_runtime.h>
#include <stdint.h>
#include <cooperative_groups.h>
namespace cg = cooperative_groups;

#define BATCH 16
#define HH 512
#define WW 512
#define WPR 16                  // 32-bit words per row
#define WPI (HH*WPR)            // 8192 words per image
#define NPIX (BATCH*HH*WW)      // 4194304
#define NBLK 2048               // kA blocks (8 px/thread, 256 thr)
#define ROWS_CTA 128            // rows per cluster CTA
#define NGRP 32                 // 4-row groups per CTA
#define SSTRIDE 18              // padded row stride
#define SBUF (ROWS_CTA*SSTRIDE) // 2304 words per buffer

// ---------------- scratch (no allocation allowed) ----------------
__device__ uint32_t g_pred[BATCH*WPI];
__device__ uint32_t g_true[BATCH*WPI];
__device__ uint32_t g_ps[BATCH*WPI];
__device__ uint32_t g_ts[BATCH*WPI];
__device__ float    g_part[4*NBLK];
__device__ float    g_cl[BATCH];
__device__ int      g_ctr;

// ---------------- kernel A: binarize + dice/focal partials -------
// 8 px/thread: 6 independent 16B loads (low MLP_p1), 4 accumulators.
__global__ __launch_bounds__(256, 7) void kA(const float* __restrict__ logits,
                                             const int*   __restrict__ tr){
    int tid = threadIdx.x;
    int gt  = blockIdx.x*256 + tid;
    int i8  = gt*8;
    int b   = i8 >> 18;
    int rem = i8 & ((1<<18)-1);

    const float4* F = (const float4*)logits;
    size_t q0 = (((size_t)(2*b) << 18) + rem) >> 2;
    size_t q1 = q0 + (1u << 16);          // +2^18 floats = +2^16 float4
    const int4* T4 = (const int4*)tr;
    size_t qt = ((size_t)i8) >> 2;

    float4 A0 = F[q0], A1 = F[q0+1];
    float4 B0 = F[q1], B1 = F[q1+1];
    int4   t0 = T4[qt], t1 = T4[qt+1];

    float L0[8] = {A0.x,A0.y,A0.z,A0.w,A1.x,A1.y,A1.z,A1.w};
    float L1[8] = {B0.x,B0.y,B0.z,B0.w,B1.x,B1.y,B1.z,B1.w};
    int   TT[8] = {t0.x,t0.y,t0.z,t0.w,t1.x,t1.y,t1.z,t1.w};

    unsigned pm = 0, tm = 0;
    float s1 = 0.f, s2 = 0.f, s3 = 0.f, s4 = 0.f;
    #pragma unroll
    for (int j = 0; j < 8; j++){
        float d = L1[j] - L0[j];
        bool pd = d > 0.f;
        bool tp = TT[j] > 0;
        pm |= (unsigned)pd << j;
        tm |= (unsigned)tp << j;
        float ad = fabsf(d);
        float e  = __expf(-ad);
        float pb = __fdividef(1.f, 1.f + e);   // sigmoid(|d|)
        float lg = -__logf(pb);                 // log(1+e^-|d|)
        float p1 = pd ? pb : 1.f - pb;
        float ce = (tp == pd) ? lg : (ad + lg);
        float pt = tp ? p1 : 1.f - p1;
        float om = 1.f - pt;
        s4 += 0.25f * om * om * ce;
        s2 += p1;
        s1 += tp ? p1 : 0.f;
        s3 += tp ? 1.f : 0.f;
    }
    ((uint8_t*)g_pred)[gt] = (uint8_t)pm;
    ((uint8_t*)g_true)[gt] = (uint8_t)tm;

    __shared__ float red[8*4];
    int lane = tid & 31, wid = tid >> 5;
    float vals[4] = {s1, s2, s3, s4};
    #pragma unroll
    for (int v = 0; v < 4; v++){
        float x = vals[v];
        #pragma unroll
        for (int o = 16; o; o >>= 1) x += __shfl_down_sync(0xffffffffu, x, o);
        if (lane == 0) red[wid*4 + v] = x;
    }
    __syncthreads();
    if (wid == 0 && lane < 4){
        float s = 0.f;
        #pragma unroll
        for (int w = 0; w < 8; w++) s += red[w*4 + lane];
        g_part[lane*NBLK + blockIdx.x] = s;
    }
}

// ---------------- kernel B: clustered, activity-gated Zhang-Suen -
template<int SUB>
__device__ __forceinline__ void subiter(
    const uint32_t* __restrict__ src, uint32_t* __restrict__ dst,
    const uint32_t* upS, const uint32_t* dnS,
    uint32_t* __restrict__ act,
    const uint32_t* __restrict__ mb_up, const uint32_t* __restrict__ mb_dn,
    uint32_t* up_mbdn, uint32_t* dn_mbup, int mbw,
    int* s_flag_p, int g, int w, uint32_t wm, int tid)
{
    uint32_t am1 = (g == 0)      ? (mb_up[0] | mb_up[1] | mb_up[2])
                                 : (act[g-1] | act[NGRP + g-1]);
    uint32_t a0  = act[g] | act[NGRP + g];
    uint32_t ap1 = (g == NGRP-1) ? (mb_dn[0] | mb_dn[1] | mb_dn[2])
                                 : (act[g+1] | act[NGRP + g+1]);
    uint32_t actv = (am1 | a0 | ap1) & wm;
    __syncthreads();

    bool changed = false;
    if (actv){
        uint32_t C[6], E[6], Wm[6];
        #pragma unroll
        for (int i = 0; i < 6; i++){
            int r = 4*g - 1 + i;
            uint32_t c, l, rr;
            if (r >= 0 && r < ROWS_CTA){
                const uint32_t* row = src + r*SSTRIDE;
                c = row[w]; l = (w > 0) ? row[w-1] : 0u; rr = (w < 15) ? row[w+1] : 0u;
            } else if (r < 0){
                if (upS){
                    const uint32_t* row = upS + (ROWS_CTA-1)*SSTRIDE;
                    c = row[w]; l = (w > 0) ? row[w-1] : 0u; rr = (w < 15) ? row[w+1] : 0u;
                } else { c = l = rr = 0u; }
            } else {
                if (dnS){
                    const uint32_t* row = dnS;
                    c = row[w]; l = (w > 0) ? row[w-1] : 0u; rr = (w < 15) ? row[w+1] : 0u;
                } else { c = l = rr = 0u; }
            }
            C[i]  = c;
            E[i]  = __funnelshift_r(c, rr, 1);
            Wm[i] = __funnelshift_l(l, c, 1);
        }
        #pragma unroll
        for (int k = 0; k < 4; k++){
            int i = k + 1;
            uint32_t cC = C[i];
            uint32_t p2 = C[i-1], p3 = E[i-1], p9 = Wm[i-1];
            uint32_t p4 = E[i],   p8 = Wm[i];
            uint32_t p6 = C[i+1], p5 = E[i+1], p7 = Wm[i+1];

            uint32_t sa = p2 ^ p3 ^ p4, ca = (p2 & p3) | (p4 & (p2 ^ p3));
            uint32_t sb = p5 ^ p6 ^ p7, cb = (p5 & p6) | (p7 & (p5 ^ p6));
            uint32_t sc = p8 ^ p9,      cc = p8 & p9;
            uint32_t S0 = sa ^ sb ^ sc, cd = (sa & sb) | (sc & (sa ^ sb));
            uint32_t t1v = ca ^ cb ^ cc, c1a = (ca & cb) | (cc & (ca ^ cb));
            uint32_t S1 = t1v ^ cd,      c1b = t1v & cd;
            uint32_t S2 = c1a ^ c1b,     S3 = c1a & c1b;
            uint32_t cond1 = (S1 | S2 | S3) & ~(S3 | (S2 & S1 & S0));

            uint32_t t0 = ~p2 & p3;
            uint32_t t1_ = ~p3 & p4;
            uint32_t t2 = ~p4 & p5;
            uint32_t t3 = ~p5 & p6;
            uint32_t t4 = ~p6 & p7;
            uint32_t t5 = ~p7 & p8;
            uint32_t t6 = ~p8 & p9;
            uint32_t t7 = ~p9 & p2;
            uint32_t onep = t0, two = 0;
            two |= onep & t1_; onep |= t1_;
            two |= onep & t2;  onep |= t2;
            two |= onep & t3;  onep |= t3;
            two |= onep & t4;  onep |= t4;
            two |= onep & t5;  onep |= t5;
            two |= onep & t6;  onep |= t6;
            two |= onep & t7;  onep |= t7;
            uint32_t condA = onep & ~two;

            uint32_t c3m, c4m;
            if (SUB == 0){ c3m = ~(p2 & p4 & p6); c4m = ~(p4 & p6 & p8); }
            else         { c3m = ~(p2 & p4 & p8); c4m = ~(p2 & p6 & p8); }

            uint32_t remv = cC & cond1 & condA & c3m & c4m;
            dst[(4*g + k)*SSTRIDE + w] = cC & ~remv;
            changed = changed || (remv != 0u);
        }
        if (changed) *s_flag_p = 1;
    }

    unsigned bal = __ballot_sync(0xffffffffu, changed);
    int lane = tid & 31;
    if (lane == 0 || lane == 16){
        uint32_t v = (lane == 0) ? (bal & 0xFFFFu) : (bal >> 16);
        act[SUB*NGRP + g] = v;
        if (g == 0       && up_mbdn) up_mbdn[mbw] = v;
        if (g == NGRP-1  && dn_mbup) dn_mbup[mbw] = v;
    }
}

__global__ void __cluster_dims__(4,1,1) __launch_bounds__(512) kB(){
    __shared__ uint32_t S[2][SBUF];
    __shared__ uint32_t act[2*NGRP];
    __shared__ uint32_t mb_up[3], mb_dn[3];
    __shared__ int s_flag[2];
    __shared__ int s_any;

    cg::cluster_group cl = cg::this_cluster();
    unsigned rank = cl.block_rank();
    int unit = blockIdx.x >> 2;
    int img  = unit >> 1;
    int sel  = unit & 1;
    const uint32_t* srcg = (sel ? g_true : g_pred) + img*WPI + rank*2048;
    uint32_t*       dstg = (sel ? g_ts   : g_ps)   + img*WPI + rank*2048;

    int tid = threadIdx.x;
    int g = tid >> 4, w = tid & 15;

    #pragma unroll
    for (int it = 0; it < 4; it++){
        int idx = tid + it*512;
        S[0][(idx>>4)*SSTRIDE + (idx&15)] = srcg[idx];
    }
    if (tid < NGRP){ act[tid] = 0xFFFFu; act[NGRP + tid] = 0xFFFFu; }
    if (tid == 0){
        uint32_t u = (rank > 0) ? 0xFFFFu : 0u;
        uint32_t d = (rank < 3) ? 0xFFFFu : 0u;
        mb_up[0] = mb_up[1] = mb_up[2] = u;
        mb_dn[0] = mb_dn[1] = mb_dn[2] = d;
        s_flag[0] = 1; s_flag[1] = 1;
    }

    uint32_t* upS    = (rank > 0) ? cl.map_shared_rank(&S[0][0], rank-1) : (uint32_t*)0;
    uint32_t* dnS    = (rank < 3) ? cl.map_shared_rank(&S[0][0], rank+1) : (uint32_t*)0;
    uint32_t* up_mbdn= (rank > 0) ? cl.map_shared_rank(&mb_dn[0], rank-1) : (uint32_t*)0;
    uint32_t* dn_mbup= (rank < 3) ? cl.map_shared_rank(&mb_up[0], rank+1) : (uint32_t*)0;
    int* fp0 = cl.map_shared_rank(&s_flag[0], 0);
    int* fp1 = cl.map_shared_rank(&s_flag[0], 1);
    int* fp2 = cl.map_shared_rank(&s_flag[0], 2);
    int* fp3 = cl.map_shared_rank(&s_flag[0], 3);

    cl.sync();

    uint32_t wm = (w == 0) ? 0x3u : (7u << (w - 1));
    int mbw = 0;
    for (int p = 0; ; p ^= 1){
        if (tid == 0){
            int q = p ^ 1;
            s_any = fp0[q] | fp1[q] | fp2[q] | fp3[q];
            s_flag[p] = 0;
        }
        __syncthreads();
        if (!s_any) break;

        subiter<0>(&S[0][0], &S[1][0],
                   upS, dnS ? dnS : (uint32_t*)0,
                   act, mb_up, mb_dn, up_mbdn, dn_mbup, mbw,
                   &s_flag[p], g, w, wm, tid);
        mbw = (mbw == 2) ? 0 : mbw + 1;
        cl.sync();

        subiter<1>(&S[1][0], &S[0][0],
                   upS ? upS + SBUF : (uint32_t*)0,
                   dnS ? dnS + SBUF : (uint32_t*)0,
                   act, mb_up, mb_dn, up_mbdn, dn_mbup, mbw,
                   &s_flag[p], g, w, wm, tid);
        mbw = (mbw == 2) ? 0 : mbw + 1;
        cl.sync();
    }

    #pragma unroll
    for (int it = 0; it < 4; it++){
        int idx = tid + it*512;
        dstg[idx] = S[0][(idx>>4)*SSTRIDE + (idx&15)];
    }
    cl.sync();
}

// ---------------- kernel CD: clDice popcounts + final combine ----
__global__ __launch_bounds__(256) void kCD(float* __restrict__ out){
    int tid = threadIdx.x;
    if (blockIdx.x < BATCH){
        int b = blockIdx.x;
        int inter = 0, sp = 0, st = 0;
        const uint4* A  = (const uint4*)(g_ps + b*WPI);
        const uint4* Cc = (const uint4*)(g_ts + b*WPI);
        for (int k = tid; k < WPI/4; k += 256){
            uint4 a = A[k], c = Cc[k];
            inter += __popc(a.x & c.x) + __popc(a.y & c.y) + __popc(a.z & c.z) + __popc(a.w & c.w);
            sp    += __popc(a.x) + __popc(a.y) + __popc(a.z) + __popc(a.w);
            st    += __popc(c.x) + __popc(c.y) + __popc(c.z) + __popc(c.w);
        }
        __shared__ int red[8*3];
        int lane = tid & 31, wid = tid >> 5;
        int v3[3] = {inter, sp, st};
        #pragma unroll
        for (int v = 0; v < 3; v++){
            int x = v3[v];
            #pragma unroll
            for (int o = 16; o; o >>= 1) x += __shfl_down_sync(0xffffffffu, x, o);
            if (lane == 0) red[wid*3 + v] = x;
        }
        __syncthreads();
        if (tid == 0){
            int ti = 0, tp = 0, tt = 0;
            #pragma unroll
            for (int w = 0; w < 8; w++){ ti += red[w*3]; tp += red[w*3+1]; tt += red[w*3+2]; }
            g_cl[b] = (2.f*(float)ti + 1e-6f) / ((float)(tp + tt) + 1e-6f);
            __threadfence();
            atomicAdd(&g_ctr, 1);
        }
    } else {
        __shared__ float red[8*4];
        int lane = tid & 31, wid = tid >> 5;
        #pragma unroll
        for (int v = 0; v < 4; v++){
            const float4* P = (const float4*)(g_part + v*NBLK);
            float4 a = P[tid], b = P[tid + 256];
            float x = ((a.x + a.y) + (a.z + a.w)) + ((b.x + b.y) + (b.z + b.w));
            #pragma unroll
            for (int o = 16; o; o >>= 1) x += __shfl_down_sync(0xffffffffu, x, o);
            if (lane == 0) red[wid*4 + v] = x;
        }
        __syncthreads();
        if (tid == 0){
            float tot[4];
            #pragma unroll
            for (int v = 0; v < 4; v++){
                float s = 0.f;
                #pragma unroll
                for (int w = 0; w < 8; w++) s += red[w*4 + v];
                tot[v] = s;
            }
            while (atomicAdd(&g_ctr, 0) < BATCH) { }
            __threadfence();
            float cls = 0.f;
            #pragma unroll
            for (int b = 0; b < BATCH; b++) cls += ((volatile float*)g_cl)[b];

            const float EPS = 1e-6f;
            float TOT = (float)NPIX;
            float s1 = tot[0], s2 = tot[1], n1 = tot[2], sf = tot[3];
            float s_i0 = (TOT - n1) - s2 + s1;       // sum p0 over true==0
            float card0 = (TOT - s2) + (TOT - n1);
            float card1 = s2 + n1;
            float dice = 1.f - 0.5f * ((2.f*s_i0 + EPS)/(card0 + EPS)
                                     + (2.f*s1 + EPS)/(card1 + EPS));
            float cl = 1.f - cls / (float)BATCH;
            float focal = sf / TOT;
            out[0] = 0.7f*cl + 0.1f*dice + 0.2f*focal;
            atomicExch(&g_ctr, 0);
        }
    }
}

// ---------------- launch -----------------------------------------
extern "C" void kernel_launch(void* const* d_in, const int* in_sizes, int n_in,
                              void* d_out, int out_size){
    const float* logits = (const float*)d_in[0];
    const int*   tr     = (const int*)d_in[1];
    kA<<<NBLK, 256>>>(logits, tr);
    kB<<<8*BATCH, 512>>>();
    kCD<<<BATCH+1, 256>>>((float*)d_out);
}